// round 7
// baseline (speedup 1.0000x reference)
#include <cuda_runtime.h>
#include <math.h>

// Problem constants (fixed by the dataset)
#define A_   16
#define SK_  2048
#define SQ_  2048
#define D_   128
#define IDM_ 128
#define RR_  3
// T_ANNEAL = 10, t_ANNEAL = 0

#define FOLD_BLOCKS 32
#define CODE_BLOCKS 8192          // 65536 rows, 8 rows (warps) per block
#define PC_TTILE    32
#define PC_BLOCKS   (A_ * (SQ_ / PC_TTILE) * (SK_ / 1024))   // 16*64*2 = 2048
#define TOTAL_BLOCKS (FOLD_BLOCKS + CODE_BLOCKS + PC_BLOCKS)

// ---------------------------------------------------------------------------
// Scratch + gates (device globals — no allocation allowed)
// ---------------------------------------------------------------------------
__device__ float  g_M[2][A_ * IDM_ * RR_];   // folded projections
__device__ float  g_c[2][A_ * RR_];          // folded bias projections
__device__ float4 g_code[2][A_ * SK_];       // [0] = Kc/3, [1] = Qc
__device__ unsigned g_F;   // fold done count (0..32)
__device__ unsigned g_C;   // code done count (0..8192)
__device__ unsigned g_P;   // pc   done count (0..2048); last resets all

__device__ __forceinline__ void spin_until(const unsigned* p, unsigned target) {
    while (__ldcg(p) < target) __nanosleep(64);
}

__device__ __forceinline__ float pc_fn(const float4 q, const float4 k) {
    float x  = fmaf(q.x, k.x, fmaf(q.y, k.y, q.z * k.z));      // Kc already /3
    float t  = x * x;
    float sg = fmaf(x, fmaf(t, -2.0833333e-5f, 0.025f), 0.5f); // sigmoid(x/10)
    return x * sg;
}

// ---------------------------------------------------------------------------
// ONE kernel: fold -> code -> pc, ordered by bid with device gates.
// ---------------------------------------------------------------------------
__global__ void __launch_bounds__(256) mega_kernel(
        const float* __restrict__ K,  const float* __restrict__ Q,
        const float* __restrict__ Wk, const float* __restrict__ bk,
        const float* __restrict__ Wq, const float* __restrict__ bq,
        const float* __restrict__ W,  float* __restrict__ out) {
    const int bid = blockIdx.x;
    const int t   = threadIdx.x;

    if (bid < FOLD_BLOCKS) {
        // ----------------- FOLD: one block per (side, a) -------------------
        const int side = bid >> 4;
        const int a    = bid & 15;
        const float* Wx = side ? Wq : Wk;
        const float* bx = side ? bq : bk;

        __shared__ float Wsh[IDM_ * RR_];      // W[a] : [128,3]
        __shared__ float red[2][IDM_ * RR_];   // two 64-e halves

        for (int i = t; i < IDM_ * RR_; i += 256) Wsh[i] = W[a * IDM_ * RR_ + i];
        __syncthreads();

        {
            const int d = t & 127;
            const int h = t >> 7;              // half 0/1 -> 64 e's each
            float a0 = 0.f, a1 = 0.f, a2 = 0.f;
#pragma unroll 8
            for (int i = 0; i < 64; i++) {
                int e = h * 64 + i;
                float w = Wx[e * D_ + d];
                a0 = fmaf(w, Wsh[e * 3 + 0], a0);
                a1 = fmaf(w, Wsh[e * 3 + 1], a1);
                a2 = fmaf(w, Wsh[e * 3 + 2], a2);
            }
            red[h][d * 3 + 0] = a0;
            red[h][d * 3 + 1] = a1;
            red[h][d * 3 + 2] = a2;
        }
        __syncthreads();

        {
            int base = a * (IDM_ * RR_);
            for (int i = t; i < IDM_ * RR_; i += 256)
                g_M[side][base + i] = red[0][i] + red[1][i];
        }

        if (t < 32) {   // bias fold on warp 0
            float c0 = 0.f, c1 = 0.f, c2 = 0.f;
#pragma unroll
            for (int e = t; e < IDM_; e += 32) {
                float b = bx[e];
                c0 = fmaf(b, Wsh[e * 3 + 0], c0);
                c1 = fmaf(b, Wsh[e * 3 + 1], c1);
                c2 = fmaf(b, Wsh[e * 3 + 2], c2);
            }
#pragma unroll
            for (int o = 16; o > 0; o >>= 1) {
                c0 += __shfl_xor_sync(0xffffffffu, c0, o);
                c1 += __shfl_xor_sync(0xffffffffu, c1, o);
                c2 += __shfl_xor_sync(0xffffffffu, c2, o);
            }
            if (t == 0) {
                g_c[side][a * RR_ + 0] = c0;
                g_c[side][a * RR_ + 1] = c1;
                g_c[side][a * RR_ + 2] = c2;
            }
        }
        __syncthreads();
        if (t == 0) { __threadfence(); atomicAdd(&g_F, 1u); }

    } else if (bid < FOLD_BLOCKS + CODE_BLOCKS) {
        // ----------------- CODE: 8 warps, 1 row each -----------------------
        if (t == 0) spin_until(&g_F, FOLD_BLOCKS);
        __syncthreads();
        __threadfence();   // acquire g_M / g_c

        int warp = (bid - FOLD_BLOCKS) * 8 + (t >> 5);
        int lane = t & 31;
        int which = (warp >= A_ * SK_) ? 1 : 0;
        int row   = which ? (warp - A_ * SK_) : warp;
        int a     = row >> 11;

        const float* X = which ? Q : K;
        const float4 x = reinterpret_cast<const float4*>(X)[row * (D_ / 4) + lane];

        const float* M = &g_M[which][a * (IDM_ * RR_) + lane * 12];
        float4 m0 = *reinterpret_cast<const float4*>(M);
        float4 m1 = *reinterpret_cast<const float4*>(M + 4);
        float4 m2 = *reinterpret_cast<const float4*>(M + 8);

        float p0 = x.x * m0.x + x.y * m0.w + x.z * m1.z + x.w * m2.y;
        float p1 = x.x * m0.y + x.y * m1.x + x.z * m1.w + x.w * m2.z;
        float p2 = x.x * m0.z + x.y * m1.y + x.z * m2.x + x.w * m2.w;

#pragma unroll
        for (int o = 16; o > 0; o >>= 1) {
            p0 += __shfl_xor_sync(0xffffffffu, p0, o);
            p1 += __shfl_xor_sync(0xffffffffu, p1, o);
            p2 += __shfl_xor_sync(0xffffffffu, p2, o);
        }
        if (lane == 0) {
            const float* c = &g_c[which][a * RR_];
            float scale = which ? 1.0f : (1.0f / 3.0f);   // fold /R into Kc
            float v0 = tanhf((p0 + c[0]) * 0.1f) * scale;
            float v1 = tanhf((p1 + c[1]) * 0.1f) * scale;
            float v2 = tanhf((p2 + c[2]) * 0.1f) * scale;
            g_code[which][row] = make_float4(v0, v1, v2, 0.f);
        }
        __syncthreads();
        if (t == 0) { __threadfence(); atomicAdd(&g_C, 1u); }

    } else {
        // ----------------- PC: 32 t-rows x 1024 s-cols ---------------------
        if (t == 0) spin_until(&g_C, CODE_BLOCKS);
        __syncthreads();
        __threadfence();   // acquire g_code

        const int pb     = bid - FOLD_BLOCKS - CODE_BLOCKS;
        const int a      = pb >> 7;            // 128 blocks per head
        const int tchunk = (pb >> 1) & 63;
        const int schunk = pb & 1;
        const int tbase  = tchunk * PC_TTILE;
        const int sbase  = schunk * 1024;

        __shared__ float4 qc_sh[PC_TTILE];
        if (t < PC_TTILE)
            qc_sh[t] = g_code[1][a * SQ_ + tbase + t];

        const float4* kc = &g_code[0][a * SK_ + sbase + t * 4];
        const float4 k0 = kc[0];
        const float4 k1 = kc[1];
        const float4 k2 = kc[2];
        const float4 k3 = kc[3];
        __syncthreads();

        size_t obase = ((size_t)(a * SQ_ + tbase)) * SK_ + (size_t)(sbase + t * 4);
#pragma unroll
        for (int j = 0; j < PC_TTILE; j++) {
            const float4 q = qc_sh[j];
            float4 o;
            o.x = pc_fn(q, k0);
            o.y = pc_fn(q, k1);
            o.z = pc_fn(q, k2);
            o.w = pc_fn(q, k3);
            *reinterpret_cast<float4*>(out + obase + (size_t)j * SK_) = o;
        }
        __syncthreads();
        if (t == 0) {
            unsigned p = atomicAdd(&g_P, 1u);
            if (p == PC_BLOCKS - 1) {          // last pc block resets gates
                g_F = 0; g_C = 0;
                __threadfence();
                g_P = 0;
                __threadfence();
            }
        }
    }
}

// ---------------------------------------------------------------------------
// Launch
// ---------------------------------------------------------------------------
extern "C" void kernel_launch(void* const* d_in, const int* in_sizes, int n_in,
                              void* d_out, int out_size) {
    const float* K  = (const float*)d_in[0];
    const float* Q  = (const float*)d_in[1];
    const float* Wk = (const float*)d_in[2];
    const float* bk = (const float*)d_in[3];
    const float* Wq = (const float*)d_in[4];
    const float* bq = (const float*)d_in[5];
    const float* W  = (const float*)d_in[6];
    float* out = (float*)d_out;

    mega_kernel<<<TOTAL_BLOCKS, 256>>>(K, Q, Wk, bk, Wq, bq, W, out);
}

// round 8
// speedup vs baseline: 1.2089x; 1.2089x over previous
#include <cuda_runtime.h>
#include <math.h>

// Problem constants (fixed by the dataset)
#define A_   16
#define SK_  2048
#define SQ_  2048
#define D_   128
#define IDM_ 128
#define RR_  3
// T_ANNEAL = 10, t_ANNEAL = 0

#define FOLD_BLOCKS 32
#define CODE_BLOCKS 4096          // 65536 rows, 8 warps x 2 rows per block
#define PC_TTILE    32
#define PC_BLOCKS   (A_ * (SQ_ / PC_TTILE) * (SK_ / 1024))   // 2048

// ---------------------------------------------------------------------------
// Scratch + gates (device globals — no allocation allowed)
// ---------------------------------------------------------------------------
__device__ float  g_M[2][A_ * IDM_ * RR_];   // folded projections
__device__ float  g_c[2][A_ * RR_];          // folded bias projections
__device__ float4 g_code[2][A_ * SK_];       // [0] = Kc/3, [1] = Qc
__device__ unsigned g_F;   // fold done count (0..32); reset by last code block
__device__ unsigned g_C;   // code done count; last block resets both

__device__ __forceinline__ void spin_until(const unsigned* p, unsigned target) {
    while (__ldcg(p) < target) __nanosleep(32);
}

// ---------------------------------------------------------------------------
// Kernel A: fold (32 blocks) + code (4096 blocks), short-range gate.
// ---------------------------------------------------------------------------
__global__ void __launch_bounds__(256) foldcode_kernel(
        const float* __restrict__ K,  const float* __restrict__ Q,
        const float* __restrict__ Wk, const float* __restrict__ bk,
        const float* __restrict__ Wq, const float* __restrict__ bq,
        const float* __restrict__ W) {
    const int bid = blockIdx.x;
    const int t   = threadIdx.x;

    if (bid < FOLD_BLOCKS) {
        // ----------------- FOLD: one block per (side, a) -------------------
        const int side = bid >> 4;
        const int a    = bid & 15;
        const float* Wx = side ? Wq : Wk;
        const float* bx = side ? bq : bk;

        __shared__ float Wsh[IDM_ * RR_];      // W[a] : [128,3]
        __shared__ float red[2][IDM_ * RR_];   // two 64-e halves

        for (int i = t; i < IDM_ * RR_; i += 256) Wsh[i] = W[a * IDM_ * RR_ + i];
        __syncthreads();

        {
            const int d = t & 127;
            const int h = t >> 7;              // half 0/1 -> 64 e's each
            float a0 = 0.f, a1 = 0.f, a2 = 0.f;
#pragma unroll 8
            for (int i = 0; i < 64; i++) {
                int e = h * 64 + i;
                float w = Wx[e * D_ + d];
                a0 = fmaf(w, Wsh[e * 3 + 0], a0);
                a1 = fmaf(w, Wsh[e * 3 + 1], a1);
                a2 = fmaf(w, Wsh[e * 3 + 2], a2);
            }
            red[h][d * 3 + 0] = a0;
            red[h][d * 3 + 1] = a1;
            red[h][d * 3 + 2] = a2;
        }
        __syncthreads();

        {
            int base = a * (IDM_ * RR_);
            for (int i = t; i < IDM_ * RR_; i += 256)
                g_M[side][base + i] = red[0][i] + red[1][i];
        }

        if (t < 32) {   // bias fold on warp 0
            float c0 = 0.f, c1 = 0.f, c2 = 0.f;
#pragma unroll
            for (int e = t; e < IDM_; e += 32) {
                float b = bx[e];
                c0 = fmaf(b, Wsh[e * 3 + 0], c0);
                c1 = fmaf(b, Wsh[e * 3 + 1], c1);
                c2 = fmaf(b, Wsh[e * 3 + 2], c2);
            }
#pragma unroll
            for (int o = 16; o > 0; o >>= 1) {
                c0 += __shfl_xor_sync(0xffffffffu, c0, o);
                c1 += __shfl_xor_sync(0xffffffffu, c1, o);
                c2 += __shfl_xor_sync(0xffffffffu, c2, o);
            }
            if (t == 0) {
                g_c[side][a * RR_ + 0] = c0;
                g_c[side][a * RR_ + 1] = c1;
                g_c[side][a * RR_ + 2] = c2;
            }
        }
        __syncthreads();
        if (t == 0) { __threadfence(); atomicAdd(&g_F, 1u); }

    } else {
        // ----------------- CODE: 8 warps, 2 rows each ----------------------
        if (t == 0) spin_until(&g_F, FOLD_BLOCKS);
        __syncthreads();
        __threadfence();   // acquire g_M / g_c

        int warp = (bid - FOLD_BLOCKS) * 8 + (t >> 5);
        int lane = t & 31;
        int row0 = warp * 2;                  // pair stays within one (side,a)
        int which = (row0 >= A_ * SK_) ? 1 : 0;
        if (which) row0 -= A_ * SK_;
        int a = row0 >> 11;

        const float* X = which ? Q : K;
        const float4 x0 = reinterpret_cast<const float4*>(X)[(row0 + 0) * (D_ / 4) + lane];
        const float4 x1 = reinterpret_cast<const float4*>(X)[(row0 + 1) * (D_ / 4) + lane];

        const float* M = &g_M[which][a * (IDM_ * RR_) + lane * 12];
        float4 m0 = *reinterpret_cast<const float4*>(M);
        float4 m1 = *reinterpret_cast<const float4*>(M + 4);
        float4 m2 = *reinterpret_cast<const float4*>(M + 8);

        float p0 = x0.x * m0.x + x0.y * m0.w + x0.z * m1.z + x0.w * m2.y;
        float p1 = x0.x * m0.y + x0.y * m1.x + x0.z * m1.w + x0.w * m2.z;
        float p2 = x0.x * m0.z + x0.y * m1.y + x0.z * m2.x + x0.w * m2.w;
        float q0 = x1.x * m0.x + x1.y * m0.w + x1.z * m1.z + x1.w * m2.y;
        float q1 = x1.x * m0.y + x1.y * m1.x + x1.z * m1.w + x1.w * m2.z;
        float q2 = x1.x * m0.z + x1.y * m1.y + x1.z * m2.x + x1.w * m2.w;

#pragma unroll
        for (int o = 16; o > 0; o >>= 1) {   // 6 interleaved chains
            p0 += __shfl_xor_sync(0xffffffffu, p0, o);
            q0 += __shfl_xor_sync(0xffffffffu, q0, o);
            p1 += __shfl_xor_sync(0xffffffffu, p1, o);
            q1 += __shfl_xor_sync(0xffffffffu, q1, o);
            p2 += __shfl_xor_sync(0xffffffffu, p2, o);
            q2 += __shfl_xor_sync(0xffffffffu, q2, o);
        }
        if (lane == 0) {
            const float* c = &g_c[which][a * RR_];
            float scale = which ? 1.0f : (1.0f / 3.0f);   // fold /R into Kc
            float c0 = c[0], c1 = c[1], c2 = c[2];
            g_code[which][a * SK_ + (row0 & 2047) + 0] = make_float4(
                tanhf((p0 + c0) * 0.1f) * scale,
                tanhf((p1 + c1) * 0.1f) * scale,
                tanhf((p2 + c2) * 0.1f) * scale, 0.f);
            g_code[which][a * SK_ + (row0 & 2047) + 1] = make_float4(
                tanhf((q0 + c0) * 0.1f) * scale,
                tanhf((q1 + c1) * 0.1f) * scale,
                tanhf((q2 + c2) * 0.1f) * scale, 0.f);
        }
        __syncthreads();
        if (t == 0) {
            unsigned c = atomicAdd(&g_C, 1u);
            if (c == CODE_BLOCKS - 1) {        // last code block resets gates
                g_F = 0;
                __threadfence();
                g_C = 0;
            }
        }
    }
}

// ---------------------------------------------------------------------------
// Kernel B: main pass.  32 t-rows x 1024 s-cols per 256-thread block.
// Kc direct LDG.128 (L2-hot); Qc via tiny smem; plain coalesced stores.
// ---------------------------------------------------------------------------
__device__ __forceinline__ float pc_fn(const float4 q, const float4 k) {
    float x  = fmaf(q.x, k.x, fmaf(q.y, k.y, q.z * k.z));      // Kc already /3
    float t  = x * x;
    float sg = fmaf(x, fmaf(t, -2.0833333e-5f, 0.025f), 0.5f); // sigmoid(x/10)
    return x * sg;
}

__global__ void __launch_bounds__(256) pc_kernel(float* __restrict__ out) {
    const int a     = blockIdx.z;
    const int tbase = blockIdx.y * PC_TTILE;
    const int sbase = blockIdx.x * 1024;
    const int tid   = threadIdx.x;

    __shared__ float4 qc_sh[PC_TTILE];
    if (tid < PC_TTILE)
        qc_sh[tid] = g_code[1][a * SQ_ + tbase + tid];

    const float4* kc = &g_code[0][a * SK_ + sbase + tid * 4];
    const float4 k0 = kc[0];
    const float4 k1 = kc[1];
    const float4 k2 = kc[2];
    const float4 k3 = kc[3];
    __syncthreads();

    size_t obase = ((size_t)(a * SQ_ + tbase)) * SK_ + (size_t)(sbase + tid * 4);
#pragma unroll
    for (int j = 0; j < PC_TTILE; j++) {
        const float4 q = qc_sh[j];
        float4 o;
        o.x = pc_fn(q, k0);
        o.y = pc_fn(q, k1);
        o.z = pc_fn(q, k2);
        o.w = pc_fn(q, k3);
        *reinterpret_cast<float4*>(out + obase + (size_t)j * SK_) = o;
    }
}

// ---------------------------------------------------------------------------
// Launch
// ---------------------------------------------------------------------------
extern "C" void kernel_launch(void* const* d_in, const int* in_sizes, int n_in,
                              void* d_out, int out_size) {
    const float* K  = (const float*)d_in[0];
    const float* Q  = (const float*)d_in[1];
    const float* Wk = (const float*)d_in[2];
    const float* bk = (const float*)d_in[3];
    const float* Wq = (const float*)d_in[4];
    const float* bq = (const float*)d_in[5];
    const float* W  = (const float*)d_in[6];
    float* out = (float*)d_out;

    foldcode_kernel<<<FOLD_BLOCKS + CODE_BLOCKS, 256>>>(K, Q, Wk, bk, Wq, bq, W);
    pc_kernel<<<dim3(SK_ / 1024, SQ_ / PC_TTILE, A_), 256>>>(out);
}